// round 11
// baseline (speedup 1.0000x reference)
#include <cuda_runtime.h>
#include <cstdint>

typedef unsigned long long ull;

#define NB      16
#define DD      128
#define NENT    100000
#define NTILES  3125           // NENT / 32
#define GRID    296            // 2 blocks per SM (148 SMs)
#define TPB     320            // 10 warps = 5 pairs
#define NW      10
#define NPAIR   5
#define ROWF4   33             // float4 per staged row (32 data + 1 pad -> conflict-free)
#define PAIR_F4 (32 * ROWF4)   // 1056 float4 per pair tile
// dynamic smem: 5 pairs * 16896 B = 84480 B (h no longer lives in smem)
#define SMEM_BYTES (NPAIR * PAIR_F4 * 16)

// ---------------- device scratch (allocation-free) ----------------
__device__ float    g_hbuf[GRID * NB * DD];  // per-block private h mirror (L1-resident)
__device__ float    g_part[NB * GRID];
__device__ unsigned g_ctr;     // tile work queue
__device__ unsigned g_done;    // grid barrier epoch counter (monotonic)

// ---------------- packed f32x2 helpers (sm_103a) ----------------
__device__ __forceinline__ ull add2(ull a, ull b) {
    ull r; asm("add.rn.f32x2 %0,%1,%2;" : "=l"(r) : "l"(a), "l"(b)); return r;
}
__device__ __forceinline__ ull fma2(ull a, ull b, ull c) {
    ull r; asm("fma.rn.f32x2 %0,%1,%2,%3;" : "=l"(r) : "l"(a), "l"(b), "l"(c)); return r;
}
__device__ __forceinline__ ull abs2(ull a) { return a & 0x7FFFFFFF7FFFFFFFull; }
__device__ __forceinline__ ull pk2(float a, float b) {
    ull r; asm("mov.b64 %0,{%1,%2};" : "=l"(r) : "f"(a), "f"(b)); return r;
}
__device__ __forceinline__ float2 upk(ull a) {
    float2 f; asm("mov.b64 {%0,%1},%2;" : "=f"(f.x), "=f"(f.y) : "l"(a)); return f;
}
__device__ __forceinline__ float wsum(float v) {
    #pragma unroll
    for (int o = 16; o; o >>= 1) v += __shfl_xor_sync(0xffffffffu, v, o);
    return v;
}
__device__ __forceinline__ unsigned sm_u32(const void* p) {
    unsigned a;
    asm("{ .reg .u64 t; cvta.to.shared.u64 t, %1; cvt.u32.u64 %0, t; }" : "=r"(a) : "l"(p));
    return a;
}
__device__ __forceinline__ void cpa16(unsigned dst, const void* src) {
    asm volatile("cp.async.cg.shared.global [%0], [%1], 16;" :: "r"(dst), "l"(src));
}
__device__ __forceinline__ void barp(int id) {   // pair barrier: 64 threads
    asm volatile("bar.sync %0, 64;" :: "r"(id) : "memory");
}

// =============== single fused kernel ===============
__global__ void __launch_bounds__(TPB, 2)
k_fused(const float* __restrict__ ent, const float* __restrict__ relemb,
        const int* __restrict__ e1w, const int* __restrict__ relw,
        float* __restrict__ out) {
    extern __shared__ float smf[];

    int tid = threadIdx.x, w = tid >> 5, l = tid & 31;
    int p = w >> 1, role = w & 1;                     // pair id, b-half role

    float4*     xs4  = (float4*)smf + p * PAIR_F4;
    unsigned    xw_u = sm_u32(xs4);
    const float4*     myrow4 = xs4 + l * ROWF4;       // lane l's entity row
    const ulonglong2* myrow2 = (const ulonglong2*)myrow4;

    // per-block private h in GLOBAL memory (L1-cached; uniform LDG = 1 wavefront)
    float* ghb = g_hbuf + (size_t)blockIdx.x * (NB * DD);

    __shared__ unsigned tsl[NPAIR];
    __shared__ float    sp[NW][8];
    __shared__ float    sinv_s[NB];

    // ---- index width detection (int64 => high words zero) ----
    int odd  = e1w[1] | e1w[3] | e1w[5] | e1w[7] | e1w[9] | e1w[11] | e1w[13] | e1w[15];
    int is64 = (odd == 0);

    // ---- build h = norm(ent[e1[b]]) + norm(rel[rel[b]]) into the global mirror ----
    for (int b = w; b < NB; b += NW) {
        long long ei, ri;
        if (is64) { ei = ((const long long*)e1w)[b]; ri = ((const long long*)relw)[b]; }
        else      { ei = (long long)e1w[b];          ri = (long long)relw[b]; }
        float4 a = ((const float4*)ent)[(size_t)ei * 32 + l];
        float sa = wsum(fmaf(a.x, a.x, fmaf(a.y, a.y, fmaf(a.z, a.z, a.w * a.w))));
        float ia = rsqrtf(fmaxf(sa, 1e-24f));
        float4 c = ((const float4*)relemb)[(size_t)ri * 32 + l];
        float sc = wsum(fmaf(c.x, c.x, fmaf(c.y, c.y, fmaf(c.z, c.z, c.w * c.w))));
        float ic = rsqrtf(fmaxf(sc, 1e-24f));
        float4 h;
        h.x = fmaf(a.x, ia, c.x * ic);
        h.y = fmaf(a.y, ia, c.y * ic);
        h.z = fmaf(a.z, ia, c.z * ic);
        h.w = fmaf(a.w, ia, c.w * ic);
        ((float4*)ghb)[b * 32 + l] = h;
    }
    __threadfence_block();
    __syncthreads();                                   // h mirror visible block-wide

    float es[8];
    #pragma unroll
    for (int j = 0; j < 8; j++) es[j] = 0.0f;
    const int bq  = role * 8;                          // my b rows: bq..bq+7
    const int bid = p + 1;                             // named barrier id
    const ulonglong2* hb = (const ulonglong2*)ghb + bq * 32;

    // ---- initial tile fetch (role-0 warp publishes to the pair) ----
    if (role == 0 && l == 0) tsl[p] = atomicAdd(&g_ctr, 1u);
    barp(bid);
    unsigned t = tsl[p];

    // =============== phase 1: dist -> exp -> store ===============
    while (t < (unsigned)NTILES) {
        int base = (int)t * 32;

        // stage my role's 16 rows (coalesced 512B rows; lane l copies 16B chunk l)
        {
            const char* src = (const char*)ent + ((size_t)base + role * 16) * 512 + l * 16;
            unsigned    dst = xw_u + (unsigned)((role * 16) * ROWF4 + l) * 16;
            #pragma unroll
            for (int k = 0; k < 16; k++)
                cpa16(dst + k * (ROWF4 * 16), src + (size_t)k * 512);
            asm volatile("cp.async.commit_group;");
        }
        // prefetch next tile index while copies are in flight
        if (role == 0 && l == 0) tsl[p] = atomicAdd(&g_ctr, 1u);
        asm volatile("cp.async.wait_group 0;");
        barp(bid);                                     // both halves staged + tsl visible
        unsigned tn = tsl[p];

        // per-lane sumsq of own entity row (conflict-free, immediate offsets)
        float s0 = 0.f, s1 = 0.f, s2 = 0.f, s3 = 0.f;
        #pragma unroll
        for (int c = 0; c < 32; c += 4) {
            float4 v0 = myrow4[c], v1 = myrow4[c+1], v2 = myrow4[c+2], v3 = myrow4[c+3];
            s0 = fmaf(v0.x, v0.x, fmaf(v0.y, v0.y, fmaf(v0.z, v0.z, fmaf(v0.w, v0.w, s0))));
            s1 = fmaf(v1.x, v1.x, fmaf(v1.y, v1.y, fmaf(v1.z, v1.z, fmaf(v1.w, v1.w, s1))));
            s2 = fmaf(v2.x, v2.x, fmaf(v2.y, v2.y, fmaf(v2.z, v2.z, fmaf(v2.w, v2.w, s2))));
            s3 = fmaf(v3.x, v3.x, fmaf(v3.y, v3.y, fmaf(v3.z, v3.z, fmaf(v3.w, v3.w, s3))));
        }
        float ss  = (s0 + s1) + (s2 + s3);
        float inv = -rsqrtf(fmaxf(ss, 1e-24f));        // diff = fma(x, -inv, h)
        ull nI = pk2(inv, inv);

        ull acc[8];
        #pragma unroll
        for (int j = 0; j < 8; j++) acc[j] = 0ull;

        // 8 groups of 4 chunks: batch x into registers, then math; h via uniform LDG
        #pragma unroll 4
        for (int g = 0; g < 8; g++) {
            ull xr[8];
            #pragma unroll
            for (int q = 0; q < 4; q++) {
                ulonglong2 xx = myrow2[g * 4 + q];     // immediate offsets
                xr[2*q]   = xx.x;
                xr[2*q+1] = xx.y;
            }
            #pragma unroll
            for (int q = 0; q < 4; q++) {
                int c = g * 4 + q;
                #pragma unroll
                for (int j = 0; j < 8; j++) {
                    ulonglong2 hh = hb[j * 32 + c];    // uniform LDG.128, L1-hot
                    acc[j] = add2(acc[j], abs2(fma2(xr[2*q],   nI, hh.x)));
                    acc[j] = add2(acc[j], abs2(fma2(xr[2*q+1], nI, hh.y)));
                }
            }
        }

        // exp + store (dist <= ~34: no max pass), coalesced per b
        {
            float* outp = out + (size_t)bq * NENT + base + l;
            #pragma unroll
            for (int j = 0; j < 8; j++) {
                float2 f = upk(acc[j]);
                float e = __expf(f.x + f.y);
                outp[(size_t)j * NENT] = e;
                es[j] += e;
            }
        }

        barp(bid);                                     // pair done reading staging
        t = tn;
    }

    // ---- warp -> block row sums ----
    #pragma unroll
    for (int j = 0; j < 8; j++) {
        float s = wsum(es[j]);
        if (l == 0) sp[w][j] = s;
    }
    __syncthreads();
    if (tid < NB) {
        int b = tid, rr = b >> 3, j = b & 7;
        float s = 0.f;
        #pragma unroll
        for (int k = 0; k < NPAIR; k++) s += sp[2 * k + rr][j];
        g_part[b * GRID + blockIdx.x] = s;
    }

    // =============== grid-wide barrier (all 296 blocks co-resident) ===============
    __syncthreads();
    if (tid == 0) {
        __threadfence();
        unsigned old = atomicAdd(&g_done, 1u);
        unsigned target = (old / GRID + 1u) * GRID;
        if (old % GRID == GRID - 1u) g_ctr = 0u;       // reset queue for next replay
        unsigned d;
        do {
            asm volatile("ld.global.acquire.gpu.u32 %0, [%1];" : "=r"(d) : "l"(&g_done));
        } while (d < target);
    }
    __syncthreads();

    // ---- reduce partials -> 1/sum per row ----
    for (int b = w; b < NB; b += NW) {
        float s = 0.f;
        for (int i = l; i < GRID; i += 32) s += g_part[b * GRID + i];
        s = wsum(s);
        if (l == 0) sinv_s[b] = 1.0f / s;
    }
    __syncthreads();

    // =============== phase 2: normalize in place (L2-hot) ===============
    {
        const int total4 = NB * NENT / 4;              // 400000
        const int chunk  = (total4 + GRID - 1) / GRID; // 1352
        int start = blockIdx.x * chunk;
        int end   = min(start + chunk, total4);
        float4* o4 = (float4*)out;
        for (int i = start + tid; i < end; i += TPB) {
            int b = i / (NENT / 4);
            float iv = sinv_s[b];
            float4 v = o4[i];
            v.x *= iv; v.y *= iv; v.z *= iv; v.w *= iv;
            o4[i] = v;
        }
    }
}

// ---------------- launch ----------------
extern "C" void kernel_launch(void* const* d_in, const int* in_sizes, int n_in,
                              void* d_out, int out_size) {
    const int*   e1     = (const int*)d_in[0];
    const int*   rel    = (const int*)d_in[1];
    // d_in[2]=X, d_in[3]=A unused by the forward pass
    const float* ent    = (const float*)d_in[4];
    const float* relemb = (const float*)d_in[5];
    float* out = (float*)d_out;

    cudaFuncSetAttribute(k_fused, cudaFuncAttributeMaxDynamicSharedMemorySize, SMEM_BYTES);
    k_fused<<<GRID, TPB, SMEM_BYTES>>>(ent, relemb, e1, rel, out);
    (void)in_sizes; (void)n_in; (void)out_size;
}

// round 12
// speedup vs baseline: 1.1540x; 1.1540x over previous
#include <cuda_runtime.h>
#include <cstdint>

typedef unsigned long long ull;

#define NB      16
#define NENT    100000
#define NT64    1563           // ceil(NENT / 64); last tile: upper 32 entities invalid
#define GRID    296            // 2 blocks per SM (148 SMs)
#define TPB     192            // 6 warps = 3 pairs
#define NW      6
#define NPAIR   3
#define ROWF4   33             // float4 per staged row (32 data + 1 pad -> conflict-free)
#define PAIR_F4 (64 * ROWF4)   // 2112 float4 per pair tile (64 entity rows)
// dynamic smem: h 8192 B + 3 pairs * 33792 B = 109568 B (x2 blocks fits 228KB SM)
#define SMEM_BYTES (8192 + NPAIR * PAIR_F4 * 16)

// ---------------- device scratch (allocation-free) ----------------
__device__ float    g_part[NB * GRID];
__device__ unsigned g_ctr;     // tile work queue
__device__ unsigned g_done;    // grid barrier epoch counter (monotonic)

// ---------------- packed f32x2 helpers (sm_103a) ----------------
__device__ __forceinline__ ull add2(ull a, ull b) {
    ull r; asm("add.rn.f32x2 %0,%1,%2;" : "=l"(r) : "l"(a), "l"(b)); return r;
}
__device__ __forceinline__ ull fma2(ull a, ull b, ull c) {
    ull r; asm("fma.rn.f32x2 %0,%1,%2,%3;" : "=l"(r) : "l"(a), "l"(b), "l"(c)); return r;
}
__device__ __forceinline__ ull abs2(ull a) { return a & 0x7FFFFFFF7FFFFFFFull; }
__device__ __forceinline__ ull pk2(float a, float b) {
    ull r; asm("mov.b64 %0,{%1,%2};" : "=l"(r) : "f"(a), "f"(b)); return r;
}
__device__ __forceinline__ float2 upk(ull a) {
    float2 f; asm("mov.b64 {%0,%1},%2;" : "=f"(f.x), "=f"(f.y) : "l"(a)); return f;
}
__device__ __forceinline__ float wsum(float v) {
    #pragma unroll
    for (int o = 16; o; o >>= 1) v += __shfl_xor_sync(0xffffffffu, v, o);
    return v;
}
__device__ __forceinline__ unsigned sm_u32(const void* p) {
    unsigned a;
    asm("{ .reg .u64 t; cvta.to.shared.u64 t, %1; cvt.u32.u64 %0, t; }" : "=r"(a) : "l"(p));
    return a;
}
__device__ __forceinline__ void cpa16(unsigned dst, const void* src) {
    asm volatile("cp.async.cg.shared.global [%0], [%1], 16;" :: "r"(dst), "l"(src));
}
__device__ __forceinline__ void barp(int id) {   // pair barrier: 64 threads
    asm volatile("bar.sync %0, 64;" :: "r"(id) : "memory");
}

// =============== single fused kernel ===============
__global__ void __launch_bounds__(TPB, 2)
k_fused(const float* __restrict__ ent, const float* __restrict__ relemb,
        const int* __restrict__ e1w, const int* __restrict__ relw,
        float* __restrict__ out) {
    extern __shared__ float smf[];
    float*      hs  = smf;                             // 16*128 floats, persistent
    ulonglong2* hs2 = (ulonglong2*)smf;                // [16][32] 16B chunks

    int tid = threadIdx.x, w = tid >> 5, l = tid & 31;
    int p = w >> 1, role = w & 1;                      // pair id, b-half role

    float4*  xs4  = (float4*)(smf + 2048) + p * PAIR_F4;
    unsigned xw_u = sm_u32(xs4);
    // lane l owns entity rows l (A) and 32+l (B) of the 64-row tile
    const float4*     rowA4 = xs4 + l * ROWF4;
    const float4*     rowB4 = xs4 + (32 + l) * ROWF4;
    const ulonglong2* rowA2 = (const ulonglong2*)rowA4;
    const ulonglong2* rowB2 = (const ulonglong2*)rowB4;

    __shared__ unsigned tsl[NPAIR];
    __shared__ float    sp[NW][8];
    __shared__ float    sinv_s[NB];

    // ---- index width detection (int64 => high words zero) ----
    int odd  = e1w[1] | e1w[3] | e1w[5] | e1w[7] | e1w[9] | e1w[11] | e1w[13] | e1w[15];
    int is64 = (odd == 0);

    // ---- build h = norm(ent[e1[b]]) + norm(rel[rel[b]]) ----
    for (int b = w; b < NB; b += NW) {
        long long ei, ri;
        if (is64) { ei = ((const long long*)e1w)[b]; ri = ((const long long*)relw)[b]; }
        else      { ei = (long long)e1w[b];          ri = (long long)relw[b]; }
        float4 a = ((const float4*)ent)[(size_t)ei * 32 + l];
        float sa = wsum(fmaf(a.x, a.x, fmaf(a.y, a.y, fmaf(a.z, a.z, a.w * a.w))));
        float ia = rsqrtf(fmaxf(sa, 1e-24f));
        float4 c = ((const float4*)relemb)[(size_t)ri * 32 + l];
        float sc = wsum(fmaf(c.x, c.x, fmaf(c.y, c.y, fmaf(c.z, c.z, c.w * c.w))));
        float ic = rsqrtf(fmaxf(sc, 1e-24f));
        float4 h;
        h.x = fmaf(a.x, ia, c.x * ic);
        h.y = fmaf(a.y, ia, c.y * ic);
        h.z = fmaf(a.z, ia, c.z * ic);
        h.w = fmaf(a.w, ia, c.w * ic);
        ((float4*)hs)[b * 32 + l] = h;
    }
    __syncthreads();

    float es[8];
    #pragma unroll
    for (int j = 0; j < 8; j++) es[j] = 0.0f;
    const int bq  = role * 8;                          // my b rows: bq..bq+7
    const int bid = p + 1;                             // named barrier id
    const ulonglong2* hb = hs2 + bq * 32;

    // ---- initial tile fetch (role-0 warp publishes to the pair) ----
    if (role == 0 && l == 0) tsl[p] = atomicAdd(&g_ctr, 1u);
    barp(bid);
    unsigned t = tsl[p];

    // =============== phase 1: dist -> exp -> store ===============
    while (t < (unsigned)NT64) {
        int base = (int)t * 64;

        // stage my role's 32 rows (of 64); lane l copies 16B chunk l of each row.
        // Source row clamped for the final partial tile (results discarded).
        {
            unsigned dst = xw_u + (unsigned)((role * 32) * ROWF4 + l) * 16;
            #pragma unroll
            for (int k = 0; k < 32; k++) {
                int rsrc = base + role * 32 + k;
                rsrc = min(rsrc, NENT - 1);
                cpa16(dst + k * (ROWF4 * 16),
                      (const char*)ent + (size_t)rsrc * 512 + l * 16);
            }
            asm volatile("cp.async.commit_group;");
        }
        // prefetch next tile index while copies are in flight
        if (role == 0 && l == 0) tsl[p] = atomicAdd(&g_ctr, 1u);
        asm volatile("cp.async.wait_group 0;");
        barp(bid);                                     // both halves staged + tsl visible
        unsigned tn = tsl[p];

        // per-lane sumsq of both owned rows (conflict-free, immediate offsets)
        float a0 = 0.f, a1 = 0.f, b0 = 0.f, b1 = 0.f;
        #pragma unroll
        for (int c = 0; c < 32; c += 2) {
            float4 va0 = rowA4[c], va1 = rowA4[c+1];
            float4 vb0 = rowB4[c], vb1 = rowB4[c+1];
            a0 = fmaf(va0.x, va0.x, fmaf(va0.y, va0.y, fmaf(va0.z, va0.z, fmaf(va0.w, va0.w, a0))));
            a1 = fmaf(va1.x, va1.x, fmaf(va1.y, va1.y, fmaf(va1.z, va1.z, fmaf(va1.w, va1.w, a1))));
            b0 = fmaf(vb0.x, vb0.x, fmaf(vb0.y, vb0.y, fmaf(vb0.z, vb0.z, fmaf(vb0.w, vb0.w, b0))));
            b1 = fmaf(vb1.x, vb1.x, fmaf(vb1.y, vb1.y, fmaf(vb1.z, vb1.z, fmaf(vb1.w, vb1.w, b1))));
        }
        float invA = -rsqrtf(fmaxf(a0 + a1, 1e-24f));  // diff = fma(x, -inv, h)
        float invB = -rsqrtf(fmaxf(b0 + b1, 1e-24f));
        ull nIA = pk2(invA, invA);
        ull nIB = pk2(invB, invB);

        ull accA[8], accB[8];
        #pragma unroll
        for (int j = 0; j < 8; j++) { accA[j] = 0ull; accB[j] = 0ull; }

        // inner: each h chunk (uniform broadcast) feeds BOTH entities' math
        #pragma unroll 4
        for (int c = 0; c < 32; c++) {
            ulonglong2 xa = rowA2[c];                  // lane-private, conflict-free
            ulonglong2 xb = rowB2[c];
            #pragma unroll
            for (int j = 0; j < 8; j++) {
                ulonglong2 hh = hb[j * 32 + c];        // uniform -> broadcast
                accA[j] = add2(accA[j], abs2(fma2(xa.x, nIA, hh.x)));
                accB[j] = add2(accB[j], abs2(fma2(xb.x, nIB, hh.x)));
                accA[j] = add2(accA[j], abs2(fma2(xa.y, nIA, hh.y)));
                accB[j] = add2(accB[j], abs2(fma2(xb.y, nIB, hh.y)));
            }
        }

        // exp + store (dist <= ~34: no max pass), coalesced per b; B-half guarded
        {
            int eA = base + l, eB = base + 32 + l;
            bool vB = (eB < NENT);
            float* outp = out + (size_t)bq * NENT;
            #pragma unroll
            for (int j = 0; j < 8; j++) {
                float2 fa = upk(accA[j]);
                float ea = __expf(fa.x + fa.y);
                outp[(size_t)j * NENT + eA] = ea;
                float2 fb = upk(accB[j]);
                float eb = __expf(fb.x + fb.y);
                if (vB) {
                    outp[(size_t)j * NENT + eB] = eb;
                    ea += eb;
                }
                es[j] += ea;
            }
        }

        barp(bid);                                     // pair done reading staging
        t = tn;
    }

    // ---- warp -> block row sums ----
    #pragma unroll
    for (int j = 0; j < 8; j++) {
        float s = wsum(es[j]);
        if (l == 0) sp[w][j] = s;
    }
    __syncthreads();
    if (tid < NB) {
        int b = tid, rr = b >> 3, j = b & 7;
        float s = 0.f;
        #pragma unroll
        for (int k = 0; k < NPAIR; k++) s += sp[2 * k + rr][j];
        g_part[b * GRID + blockIdx.x] = s;
    }

    // =============== grid-wide barrier (all 296 blocks co-resident) ===============
    __syncthreads();
    if (tid == 0) {
        __threadfence();
        unsigned old = atomicAdd(&g_done, 1u);
        unsigned target = (old / GRID + 1u) * GRID;
        if (old % GRID == GRID - 1u) g_ctr = 0u;       // reset queue for next replay
        unsigned d;
        do {
            asm volatile("ld.global.acquire.gpu.u32 %0, [%1];" : "=r"(d) : "l"(&g_done));
        } while (d < target);
    }
    __syncthreads();

    // ---- reduce partials -> 1/sum per row ----
    for (int b = w; b < NB; b += NW) {
        float s = 0.f;
        for (int i = l; i < GRID; i += 32) s += g_part[b * GRID + i];
        s = wsum(s);
        if (l == 0) sinv_s[b] = 1.0f / s;
    }
    __syncthreads();

    // =============== phase 2: normalize in place (L2-hot) ===============
    {
        const int total4 = NB * NENT / 4;              // 400000
        const int chunk  = (total4 + GRID - 1) / GRID; // 1352
        int start = blockIdx.x * chunk;
        int end   = min(start + chunk, total4);
        float4* o4 = (float4*)out;
        for (int i = start + tid; i < end; i += TPB) {
            int b = i / (NENT / 4);
            float iv = sinv_s[b];
            float4 v = o4[i];
            v.x *= iv; v.y *= iv; v.z *= iv; v.w *= iv;
            o4[i] = v;
        }
    }
}

// ---------------- launch ----------------
extern "C" void kernel_launch(void* const* d_in, const int* in_sizes, int n_in,
                              void* d_out, int out_size) {
    const int*   e1     = (const int*)d_in[0];
    const int*   rel    = (const int*)d_in[1];
    // d_in[2]=X, d_in[3]=A unused by the forward pass
    const float* ent    = (const float*)d_in[4];
    const float* relemb = (const float*)d_in[5];
    float* out = (float*)d_out;

    cudaFuncSetAttribute(k_fused, cudaFuncAttributeMaxDynamicSharedMemorySize, SMEM_BYTES);
    k_fused<<<GRID, TPB, SMEM_BYTES>>>(ent, relemb, e1, rel, out);
    (void)in_sizes; (void)n_in; (void)out_size;
}

// round 13
// speedup vs baseline: 1.2962x; 1.1232x over previous
#include <cuda_runtime.h>
#include <cstdint>

typedef unsigned long long ull;

#define NB      16
#define NENT    100000
#define NTILES  3125           // NENT / 32
#define NSTAT   2960           // 1480 pairs * 2 static tiles
#define GRID    296            // 2 blocks per SM (148 SMs)
#define TPB     320            // 10 warps = 5 pairs
#define NW      10
#define NPAIR   5
#define ROWF4   33             // float4 per staged row (32 data + 1 pad -> conflict-free)
#define PAIR_F4 (32 * ROWF4)   // 1056 float4 per pair tile
// dynamic smem: h 8192 B + 5 pairs * 16896 B = 92672 B
#define SMEM_BYTES (8192 + NPAIR * PAIR_F4 * 16)

// ---------------- device scratch (allocation-free) ----------------
__device__ float    g_part[NB * GRID];
__device__ unsigned g_qctr;    // remainder-tile work queue (starts/resets to 0)
__device__ unsigned g_done;    // grid barrier epoch counter (monotonic)

// ---------------- packed f32x2 helpers (sm_103a) ----------------
__device__ __forceinline__ ull add2(ull a, ull b) {
    ull r; asm("add.rn.f32x2 %0,%1,%2;" : "=l"(r) : "l"(a), "l"(b)); return r;
}
__device__ __forceinline__ ull fma2(ull a, ull b, ull c) {
    ull r; asm("fma.rn.f32x2 %0,%1,%2,%3;" : "=l"(r) : "l"(a), "l"(b), "l"(c)); return r;
}
__device__ __forceinline__ ull abs2(ull a) { return a & 0x7FFFFFFF7FFFFFFFull; }
__device__ __forceinline__ ull pk2(float a, float b) {
    ull r; asm("mov.b64 %0,{%1,%2};" : "=l"(r) : "f"(a), "f"(b)); return r;
}
__device__ __forceinline__ float2 upk(ull a) {
    float2 f; asm("mov.b64 {%0,%1},%2;" : "=f"(f.x), "=f"(f.y) : "l"(a)); return f;
}
__device__ __forceinline__ float wsum(float v) {
    #pragma unroll
    for (int o = 16; o; o >>= 1) v += __shfl_xor_sync(0xffffffffu, v, o);
    return v;
}
__device__ __forceinline__ unsigned sm_u32(const void* p) {
    unsigned a;
    asm("{ .reg .u64 t; cvta.to.shared.u64 t, %1; cvt.u32.u64 %0, t; }" : "=r"(a) : "l"(p));
    return a;
}
__device__ __forceinline__ void cpa16(unsigned dst, const void* src) {
    asm volatile("cp.async.cg.shared.global [%0], [%1], 16;" :: "r"(dst), "l"(src));
}
__device__ __forceinline__ void barp(int id) {   // pair barrier: 64 threads
    asm volatile("bar.sync %0, 64;" :: "r"(id) : "memory");
}

// =============== single fused kernel ===============
__global__ void __launch_bounds__(TPB, 2)
k_fused(const float* __restrict__ ent, const float* __restrict__ relemb,
        const int* __restrict__ e1w, const int* __restrict__ relw,
        float* __restrict__ out) {
    extern __shared__ float smf[];
    float*      hs  = smf;                             // 16*128 floats, persistent
    ulonglong2* hs2 = (ulonglong2*)smf;                // [16][32] 16B chunks

    int tid = threadIdx.x, w = tid >> 5, l = tid & 31;
    int p = w >> 1, role = w & 1;                      // pair id, b-half role

    float4*     xs4  = (float4*)(smf + 2048) + p * PAIR_F4;
    unsigned    xw_u = sm_u32(xs4);
    const float4*     myrow4 = xs4 + l * ROWF4;        // lane l's entity row
    const ulonglong2* myrow2 = (const ulonglong2*)myrow4;

    __shared__ unsigned tsl[NPAIR];
    __shared__ float    sp[NW][8];
    __shared__ float    sinv_s[NB];

    // ---- index width detection (int64 => high words zero) ----
    int odd  = e1w[1] | e1w[3] | e1w[5] | e1w[7] | e1w[9] | e1w[11] | e1w[13] | e1w[15];
    int is64 = (odd == 0);

    // ---- build h = norm(ent[e1[b]]) + norm(rel[rel[b]]) ----
    for (int b = w; b < NB; b += NW) {
        long long ei, ri;
        if (is64) { ei = ((const long long*)e1w)[b]; ri = ((const long long*)relw)[b]; }
        else      { ei = (long long)e1w[b];          ri = (long long)relw[b]; }
        float4 a = ((const float4*)ent)[(size_t)ei * 32 + l];
        float sa = wsum(fmaf(a.x, a.x, fmaf(a.y, a.y, fmaf(a.z, a.z, a.w * a.w))));
        float ia = rsqrtf(fmaxf(sa, 1e-24f));
        float4 c = ((const float4*)relemb)[(size_t)ri * 32 + l];
        float sc = wsum(fmaf(c.x, c.x, fmaf(c.y, c.y, fmaf(c.z, c.z, c.w * c.w))));
        float ic = rsqrtf(fmaxf(sc, 1e-24f));
        float4 h;
        h.x = fmaf(a.x, ia, c.x * ic);
        h.y = fmaf(a.y, ia, c.y * ic);
        h.z = fmaf(a.z, ia, c.z * ic);
        h.w = fmaf(a.w, ia, c.w * ic);
        ((float4*)hs)[b * 32 + l] = h;
    }
    __syncthreads();

    float es[8];
    #pragma unroll
    for (int j = 0; j < 8; j++) es[j] = 0.0f;
    const int bq  = role * 8;                          // my b rows: bq..bq+7
    const int bid = p + 1;                             // named barrier id
    const ulonglong2* hb = hs2 + bq * 32;

    // ---- static first tile: no atomic, no communication ----
    const unsigned gp = (unsigned)blockIdx.x * NPAIR + (unsigned)p;  // 0..1479
    unsigned t = 2u * gp;                              // always < NSTAT

    // =============== phase 1: dist -> exp -> store ===============
    while (t < (unsigned)NTILES) {
        int base = (int)t * 32;
        bool first = (t == 2u * gp);

        // stage my role's 16 rows (coalesced 512B rows; lane l copies 16B chunk l)
        {
            const char* src = (const char*)ent + ((size_t)base + role * 16) * 512 + l * 16;
            unsigned    dst = xw_u + (unsigned)((role * 16) * ROWF4 + l) * 16;
            #pragma unroll
            for (int k = 0; k < 16; k++)
                cpa16(dst + k * (ROWF4 * 16), src + (size_t)k * 512);
            asm volatile("cp.async.commit_group;");
        }
        // next tile: second static tile is known locally; afterwards work-steal
        // the 165 remainder tiles (atomics are rare and time-staggered).
        if (!first && role == 0 && l == 0)
            tsl[p] = NSTAT + atomicAdd(&g_qctr, 1u);
        asm volatile("cp.async.wait_group 0;");
        barp(bid);                                     // staged + tsl visible
        unsigned tn = first ? (t + 1u) : tsl[p];

        // per-lane sumsq of own entity row (conflict-free, immediate offsets)
        float s0 = 0.f, s1 = 0.f, s2 = 0.f, s3 = 0.f;
        #pragma unroll
        for (int c = 0; c < 32; c += 4) {
            float4 v0 = myrow4[c], v1 = myrow4[c+1], v2 = myrow4[c+2], v3 = myrow4[c+3];
            s0 = fmaf(v0.x, v0.x, fmaf(v0.y, v0.y, fmaf(v0.z, v0.z, fmaf(v0.w, v0.w, s0))));
            s1 = fmaf(v1.x, v1.x, fmaf(v1.y, v1.y, fmaf(v1.z, v1.z, fmaf(v1.w, v1.w, s1))));
            s2 = fmaf(v2.x, v2.x, fmaf(v2.y, v2.y, fmaf(v2.z, v2.z, fmaf(v2.w, v2.w, s2))));
            s3 = fmaf(v3.x, v3.x, fmaf(v3.y, v3.y, fmaf(v3.z, v3.z, fmaf(v3.w, v3.w, s3))));
        }
        float ss  = (s0 + s1) + (s2 + s3);
        float inv = -rsqrtf(fmaxf(ss, 1e-24f));        // diff = fma(x, -inv, h)
        ull nI = pk2(inv, inv);

        ull acc[8];
        #pragma unroll
        for (int j = 0; j < 8; j++) acc[j] = 0ull;

        // 8 groups of 4 chunks: batch x into registers, then pure math
        #pragma unroll 4
        for (int g = 0; g < 8; g++) {
            ull xr[8];
            #pragma unroll
            for (int q = 0; q < 4; q++) {
                ulonglong2 xx = myrow2[g * 4 + q];     // immediate offsets
                xr[2*q]   = xx.x;
                xr[2*q+1] = xx.y;
            }
            #pragma unroll
            for (int q = 0; q < 4; q++) {
                int c = g * 4 + q;
                #pragma unroll
                for (int j = 0; j < 8; j++) {
                    ulonglong2 hh = hb[j * 32 + c];    // uniform -> broadcast, imm offs
                    acc[j] = add2(acc[j], abs2(fma2(xr[2*q],   nI, hh.x)));
                    acc[j] = add2(acc[j], abs2(fma2(xr[2*q+1], nI, hh.y)));
                }
            }
        }

        // exp + store (dist <= ~34: no max pass), coalesced per b
        {
            float* outp = out + (size_t)bq * NENT + base + l;
            #pragma unroll
            for (int j = 0; j < 8; j++) {
                float2 f = upk(acc[j]);
                float e = __expf(f.x + f.y);
                outp[(size_t)j * NENT] = e;
                es[j] += e;
            }
        }

        barp(bid);                                     // pair done reading staging
        t = tn;
    }

    // ---- warp -> block row sums ----
    #pragma unroll
    for (int j = 0; j < 8; j++) {
        float s = wsum(es[j]);
        if (l == 0) sp[w][j] = s;
    }
    __syncthreads();
    if (tid < NB) {
        int b = tid, rr = b >> 3, j = b & 7;
        float s = 0.f;
        #pragma unroll
        for (int k = 0; k < NPAIR; k++) s += sp[2 * k + rr][j];
        g_part[b * GRID + blockIdx.x] = s;
    }

    // =============== grid-wide barrier (all 296 blocks co-resident) ===============
    __syncthreads();
    if (tid == 0) {
        __threadfence();
        unsigned old = atomicAdd(&g_done, 1u);
        unsigned target = (old / GRID + 1u) * GRID;
        if (old % GRID == GRID - 1u) g_qctr = 0u;      // reset queue for next replay
        unsigned d;
        do {
            asm volatile("ld.global.acquire.gpu.u32 %0, [%1];" : "=r"(d) : "l"(&g_done));
        } while (d < target);
    }
    __syncthreads();

    // ---- reduce partials -> 1/sum per row ----
    for (int b = w; b < NB; b += NW) {
        float s = 0.f;
        for (int i = l; i < GRID; i += 32) s += g_part[b * GRID + i];
        s = wsum(s);
        if (l == 0) sinv_s[b] = 1.0f / s;
    }
    __syncthreads();

    // =============== phase 2: normalize in place (L2-hot) ===============
    {
        const int total4 = NB * NENT / 4;              // 400000
        const int chunk  = (total4 + GRID - 1) / GRID; // 1352
        int start = blockIdx.x * chunk;
        int end   = min(start + chunk, total4);
        float4* o4 = (float4*)out;
        for (int i = start + tid; i < end; i += TPB) {
            int b = i / (NENT / 4);
            float iv = sinv_s[b];
            float4 v = o4[i];
            v.x *= iv; v.y *= iv; v.z *= iv; v.w *= iv;
            o4[i] = v;
        }
    }
}

// ---------------- launch ----------------
extern "C" void kernel_launch(void* const* d_in, const int* in_sizes, int n_in,
                              void* d_out, int out_size) {
    const int*   e1     = (const int*)d_in[0];
    const int*   rel    = (const int*)d_in[1];
    // d_in[2]=X, d_in[3]=A unused by the forward pass
    const float* ent    = (const float*)d_in[4];
    const float* relemb = (const float*)d_in[5];
    float* out = (float*)d_out;

    cudaFuncSetAttribute(k_fused, cudaFuncAttributeMaxDynamicSharedMemorySize, SMEM_BYTES);
    k_fused<<<GRID, TPB, SMEM_BYTES>>>(ent, relemb, e1, rel, out);
    (void)in_sizes; (void)n_in; (void)out_size;
}